// round 1
// baseline (speedup 1.0000x reference)
#include <cuda_runtime.h>
#include <math.h>

// ---------------- problem constants ----------------
#define TOPK 6
#define NE   64
#define ND   2048
#define NF   1408
#define NFS  2816
#define NTOK 8192
#define NA   (NTOK*TOPK)   // 49152 routed assignments
#define CAP  1536          // per-expert capacity (never binds in practice)

// ---------------- scratch (device globals; no allocation) ----------------
__device__ int   g_counts[NE];
__device__ int   g_offsets[NE];
__device__ int   g_cursor[NE];
__device__ int   g_tidx[NA];
__device__ float g_tw[NA];
__device__ int   g_stok[NA];     // sorted assignment -> token index
__device__ int   g_a2p[NA];      // assignment -> sorted position (-1 if dropped)
__device__ float g_g [(size_t)NA * NF];    // gate proj / act (in place)
__device__ float g_u [(size_t)NA * NF];    // up proj
__device__ float g_eo[(size_t)NA * ND];    // expert output rows
__device__ float g_sg[(size_t)NTOK * NFS]; // shared gate / act
__device__ float g_su[(size_t)NTOK * NFS]; // shared up

// ---------------- small kernels ----------------
__global__ void zero_kernel() {
    int i = threadIdx.x;
    if (i < NE) { g_counts[i] = 0; g_cursor[i] = 0; }
}

// Router: logits = x @ gate_w^T; top-6; weights = softmax over top-6 logits.
__global__ void router_kernel(const float* __restrict__ x,
                              const float* __restrict__ gw)
{
    int t = blockIdx.x;
    __shared__ float xs[ND];
    __shared__ float logits[NE];
    const float* xr = x + (size_t)t * ND;
    for (int i = threadIdx.x; i < ND; i += blockDim.x) xs[i] = xr[i];
    __syncthreads();

    int warp = threadIdx.x >> 5, lane = threadIdx.x & 31;
    #pragma unroll
    for (int e8 = 0; e8 < 8; e8++) {
        int e = warp * 8 + e8;
        const float* w = gw + (size_t)e * ND;
        float s = 0.f;
        for (int i = lane; i < ND; i += 32) s += xs[i] * w[i];
        #pragma unroll
        for (int o = 16; o; o >>= 1) s += __shfl_down_sync(0xffffffffu, s, o);
        if (lane == 0) logits[e] = s;
    }
    __syncthreads();

    if (threadIdx.x == 0) {
        int idx6[TOPK]; float val6[TOPK];
        unsigned long long used = 0ull;
        for (int k = 0; k < TOPK; k++) {
            float best = -INFINITY; int bi = 0;
            for (int e = 0; e < NE; e++) {
                if (!((used >> e) & 1ull) && logits[e] > best) { best = logits[e]; bi = e; }
            }
            used |= 1ull << bi; idx6[k] = bi; val6[k] = best;
        }
        float m = val6[0], sum = 0.f, w6[TOPK];
        #pragma unroll
        for (int k = 0; k < TOPK; k++) { w6[k] = expf(val6[k] - m); sum += w6[k]; }
        float inv = 1.f / sum;
        #pragma unroll
        for (int k = 0; k < TOPK; k++) {
            g_tidx[t * TOPK + k] = idx6[k];
            g_tw  [t * TOPK + k] = w6[k] * inv;
            atomicAdd(&g_counts[idx6[k]], 1);
        }
    }
}

__global__ void prefix_kernel() {
    if (threadIdx.x == 0) {
        int acc = 0;
        for (int e = 0; e < NE; e++) { g_offsets[e] = acc; acc += g_counts[e]; }
    }
}

__global__ void scatter_kernel() {
    int a = blockIdx.x * blockDim.x + threadIdx.x;
    if (a >= NA) return;
    int e = g_tidx[a];
    int slot = atomicAdd(&g_cursor[e], 1);
    if (slot < CAP) {
        int p = g_offsets[e] + slot;
        g_stok[p] = a / TOPK;
        g_a2p[a] = p;
    } else {
        g_a2p[a] = -1;
    }
}

// ---------------- generic SGEMM: C[m][n] = sum_k A[m][k]*B[n][k] ----------------
// expert mode (offsets != null): e = blockIdx.z; rows live at [offsets[e], +min(counts,CAP))
// gather mode (rowmap != null): physical A row = rowmap[rowbase + m]
#define BM 128
#define BN 128
#define BK 8

__global__ __launch_bounds__(256, 2)
void sgemm_tn(const float* __restrict__ A, int lda,
              const float* __restrict__ B,
              float* __restrict__ C, int ldc,
              int M, int Ntot, int K,
              const int* __restrict__ rowmap,
              const int* __restrict__ offsets,
              const int* __restrict__ counts)
{
    int rowbase = 0;
    if (offsets) {
        int e = blockIdx.z;
        rowbase = offsets[e];
        M = min(counts[e], CAP);
        B += (size_t)e * Ntot * K;
    }
    int m0 = blockIdx.y * BM;
    if (m0 >= M) return;
    int n0 = blockIdx.x * BN;

    __shared__ float As[BK][BM];
    __shared__ float Bs[BK][BN];

    int tid = threadIdx.x;
    int lr = tid >> 1;            // 0..127
    int lc = (tid & 1) * 4;       // 0 or 4

    int mclamp = min(m0 + lr, M - 1);
    int phys = rowmap ? rowmap[rowbase + mclamp] : (rowbase + mclamp);
    const float* arow = A + (size_t)phys * lda;
    const float* brow = B + (size_t)(n0 + lr) * K;

    int tx = tid & 15;
    int ty = tid >> 4;

    float acc[8][8];
    #pragma unroll
    for (int i = 0; i < 8; i++)
        #pragma unroll
        for (int j = 0; j < 8; j++) acc[i][j] = 0.f;

    for (int k0 = 0; k0 < K; k0 += BK) {
        float4 av = *(const float4*)(arow + k0 + lc);
        float4 bv = *(const float4*)(brow + k0 + lc);
        As[lc + 0][lr] = av.x; As[lc + 1][lr] = av.y;
        As[lc + 2][lr] = av.z; As[lc + 3][lr] = av.w;
        Bs[lc + 0][lr] = bv.x; Bs[lc + 1][lr] = bv.y;
        Bs[lc + 2][lr] = bv.z; Bs[lc + 3][lr] = bv.w;
        __syncthreads();
        #pragma unroll
        for (int k = 0; k < BK; k++) {
            float4 a0 = *(const float4*)&As[k][ty * 8];
            float4 a1 = *(const float4*)&As[k][ty * 8 + 4];
            float4 b0 = *(const float4*)&Bs[k][tx * 8];
            float4 b1 = *(const float4*)&Bs[k][tx * 8 + 4];
            float ar[8] = {a0.x, a0.y, a0.z, a0.w, a1.x, a1.y, a1.z, a1.w};
            float br[8] = {b0.x, b0.y, b0.z, b0.w, b1.x, b1.y, b1.z, b1.w};
            #pragma unroll
            for (int i = 0; i < 8; i++)
                #pragma unroll
                for (int j = 0; j < 8; j++)
                    acc[i][j] += ar[i] * br[j];
        }
        __syncthreads();
    }

    #pragma unroll
    for (int i = 0; i < 8; i++) {
        int m = m0 + ty * 8 + i;
        if (m < M) {
            float* crow = C + (size_t)(rowbase + m) * ldc + n0 + tx * 8;
            *(float4*)(crow)     = make_float4(acc[i][0], acc[i][1], acc[i][2], acc[i][3]);
            *(float4*)(crow + 4) = make_float4(acc[i][4], acc[i][5], acc[i][6], acc[i][7]);
        }
    }
}

// act = silu(g) * u, written into g
__global__ void swiglu_ew(float* __restrict__ g, const float* __restrict__ u, size_t n) {
    size_t i = (size_t)blockIdx.x * blockDim.x + threadIdx.x;
    if (i >= n) return;
    float gv = g[i];
    g[i] = (gv / (1.f + expf(-gv))) * u[i];
}

// out[t][d] += sum_k w(t,k) * eo[pos(t,k)][d]   (out already holds shared-expert result)
__global__ void combine_kernel(float* __restrict__ out) {
    int t = blockIdx.y;
    int d = blockIdx.x * blockDim.x + threadIdx.x;
    float s = out[(size_t)t * ND + d];
    #pragma unroll
    for (int k = 0; k < TOPK; k++) {
        int p = g_a2p[t * TOPK + k];
        if (p >= 0) s += g_tw[t * TOPK + k] * g_eo[(size_t)p * ND + d];
    }
    out[(size_t)t * ND + d] = s;
}

// ---------------- launch ----------------
extern "C" void kernel_launch(void* const* d_in, const int* in_sizes, int n_in,
                              void* d_out, int out_size)
{
    const float* x       = (const float*)d_in[0];
    const float* gate_w  = (const float*)d_in[1];
    const float* w_gate  = (const float*)d_in[2];
    const float* w_up    = (const float*)d_in[3];
    const float* w_down  = (const float*)d_in[4];
    const float* sh_gate = (const float*)d_in[5];
    const float* sh_up   = (const float*)d_in[6];
    const float* sh_down = (const float*)d_in[7];
    float* out = (float*)d_out;

    void *pg, *pu, *peo, *psg, *psu, *pstok, *poff, *pcnt;
    cudaGetSymbolAddress(&pg,   g_g);
    cudaGetSymbolAddress(&pu,   g_u);
    cudaGetSymbolAddress(&peo,  g_eo);
    cudaGetSymbolAddress(&psg,  g_sg);
    cudaGetSymbolAddress(&psu,  g_su);
    cudaGetSymbolAddress(&pstok, g_stok);
    cudaGetSymbolAddress(&poff, g_offsets);
    cudaGetSymbolAddress(&pcnt, g_counts);
    float* gbuf = (float*)pg;  float* ubuf = (float*)pu;  float* eo = (float*)peo;
    float* sg = (float*)psg;   float* su = (float*)psu;
    int* stok = (int*)pstok;   int* offs = (int*)poff;    int* cnts = (int*)pcnt;

    // 1) router + dispatch bookkeeping
    zero_kernel<<<1, 64>>>();
    router_kernel<<<NTOK, 256>>>(x, gate_w);
    prefix_kernel<<<1, 1>>>();
    scatter_kernel<<<(NA + 255) / 256, 256>>>();

    // 2) routed expert GEMMs (gathered rows, grouped by expert)
    {
        dim3 grid(NF / BN, CAP / BM, NE);
        sgemm_tn<<<grid, 256>>>(x, ND, w_gate, gbuf, NF, 0, NF, ND, stok, offs, cnts);
        sgemm_tn<<<grid, 256>>>(x, ND, w_up,   ubuf, NF, 0, NF, ND, stok, offs, cnts);
    }
    {
        size_t n = (size_t)NA * NF;
        swiglu_ew<<<(unsigned)((n + 255) / 256), 256>>>(gbuf, ubuf, n);
    }
    {
        dim3 grid(ND / BN, CAP / BM, NE);
        sgemm_tn<<<grid, 256>>>(gbuf, NF, w_down, eo, ND, 0, ND, NF, nullptr, offs, cnts);
    }

    // 3) shared expert (writes d_out directly, acts as output initializer)
    {
        dim3 grid(NFS / BN, NTOK / BM, 1);
        sgemm_tn<<<grid, 256>>>(x, ND, sh_gate, sg, NFS, NTOK, NFS, ND, nullptr, nullptr, nullptr);
        sgemm_tn<<<grid, 256>>>(x, ND, sh_up,   su, NFS, NTOK, NFS, ND, nullptr, nullptr, nullptr);
    }
    {
        size_t n = (size_t)NTOK * NFS;
        swiglu_ew<<<(unsigned)((n + 255) / 256), 256>>>(sg, su, n);
    }
    {
        dim3 grid(ND / BN, NTOK / BM, 1);
        sgemm_tn<<<grid, 256>>>(sg, NFS, sh_down, out, ND, NTOK, ND, NFS, nullptr, nullptr, nullptr);
    }

    // 4) weighted combine of routed expert outputs into d_out
    {
        dim3 grid(ND / 256, NTOK);
        combine_kernel<<<grid, 256>>>(out);
    }
}

// round 2
// speedup vs baseline: 3.0901x; 3.0901x over previous
#include <cuda_runtime.h>
#include <math.h>

// ---------------- problem constants ----------------
#define TOPK 6
#define NE   64
#define ND   2048
#define NF   1408
#define NFS  2816
#define NTOK 8192
#define NA   (NTOK*TOPK)   // 49152 routed assignments
#define CAP  1536

// ---------------- scratch (device globals) ----------------
__device__ int   g_counts[NE];
__device__ int   g_offsets[NE];
__device__ int   g_cursor[NE];
__device__ int   g_tidx[NA];
__device__ float g_tw[NA];
__device__ int   g_stok[NA];
__device__ int   g_a2p[NA];
__device__ float g_g [(size_t)NA * NF];
__device__ float g_u [(size_t)NA * NF];
__device__ float g_eo[(size_t)NA * ND];
__device__ float g_sg[(size_t)NTOK * NFS];
__device__ float g_su[(size_t)NTOK * NFS];

// ---------------- small kernels ----------------
__global__ void zero_kernel() {
    int i = threadIdx.x;
    if (i < NE) { g_counts[i] = 0; g_cursor[i] = 0; }
}

__global__ void router_kernel(const float* __restrict__ x,
                              const float* __restrict__ gw)
{
    int t = blockIdx.x;
    __shared__ float xs[ND];
    __shared__ float logits[NE];
    const float* xr = x + (size_t)t * ND;
    for (int i = threadIdx.x; i < ND; i += blockDim.x) xs[i] = xr[i];
    __syncthreads();

    int warp = threadIdx.x >> 5, lane = threadIdx.x & 31;
    #pragma unroll
    for (int e8 = 0; e8 < 8; e8++) {
        int e = warp * 8 + e8;
        const float* w = gw + (size_t)e * ND;
        float s = 0.f;
        for (int i = lane; i < ND; i += 32) s += xs[i] * w[i];
        #pragma unroll
        for (int o = 16; o; o >>= 1) s += __shfl_down_sync(0xffffffffu, s, o);
        if (lane == 0) logits[e] = s;
    }
    __syncthreads();

    if (threadIdx.x == 0) {
        int idx6[TOPK]; float val6[TOPK];
        unsigned long long used = 0ull;
        for (int k = 0; k < TOPK; k++) {
            float best = -INFINITY; int bi = 0;
            for (int e = 0; e < NE; e++) {
                if (!((used >> e) & 1ull) && logits[e] > best) { best = logits[e]; bi = e; }
            }
            used |= 1ull << bi; idx6[k] = bi; val6[k] = best;
        }
        float m = val6[0], sum = 0.f, w6[TOPK];
        #pragma unroll
        for (int k = 0; k < TOPK; k++) { w6[k] = expf(val6[k] - m); sum += w6[k]; }
        float inv = 1.f / sum;
        #pragma unroll
        for (int k = 0; k < TOPK; k++) {
            g_tidx[t * TOPK + k] = idx6[k];
            g_tw  [t * TOPK + k] = w6[k] * inv;
            atomicAdd(&g_counts[idx6[k]], 1);
        }
    }
}

__global__ void prefix_kernel() {
    if (threadIdx.x == 0) {
        int acc = 0;
        for (int e = 0; e < NE; e++) { g_offsets[e] = acc; acc += g_counts[e]; }
    }
}

__global__ void scatter_kernel() {
    int a = blockIdx.x * blockDim.x + threadIdx.x;
    if (a >= NA) return;
    int e = g_tidx[a];
    int slot = atomicAdd(&g_cursor[e], 1);
    if (slot < CAP) {
        int p = g_offsets[e] + slot;
        g_stok[p] = a / TOPK;
        g_a2p[a] = p;
    } else {
        g_a2p[a] = -1;
    }
}

// ---------------- tf32 tensor-core GEMM ----------------
// C[m][n] = sum_k A[m][k] * B[n][k]  (both row-major, B is a weight [N][K])
// expert mode (offsets != null): e = blockIdx.z, rows at [offsets[e], +min(counts,CAP))
// gather mode (rowmap != null): physical A row = rowmap[rowbase + m]
#define BM 128
#define BN 128
#define BK 32
#define LDS 36   // padded k-stride in words: conflict-free fills and frag loads

__device__ __forceinline__ unsigned f2tf32(float f) {
    unsigned u;
    asm volatile("cvt.rna.tf32.f32 %0, %1;" : "=r"(u) : "f"(f));
    return u;
}

__device__ __forceinline__ void mma_tf32(float d[4], const unsigned a[4],
                                         const unsigned b[2], const float c[4]) {
    asm volatile(
        "mma.sync.aligned.m16n8k8.row.col.f32.tf32.tf32.f32 "
        "{%0,%1,%2,%3},{%4,%5,%6,%7},{%8,%9},{%10,%11,%12,%13};\n"
        : "=f"(d[0]), "=f"(d[1]), "=f"(d[2]), "=f"(d[3])
        : "r"(a[0]), "r"(a[1]), "r"(a[2]), "r"(a[3]),
          "r"(b[0]), "r"(b[1]),
          "f"(c[0]), "f"(c[1]), "f"(c[2]), "f"(c[3]));
}

__global__ __launch_bounds__(256)
void gemm_tf32(const float* __restrict__ A, int lda,
               const float* __restrict__ B,
               float* __restrict__ C, int ldc,
               int M, int Ntot, int K,
               const int* __restrict__ rowmap,
               const int* __restrict__ offsets,
               const int* __restrict__ counts)
{
    int rowbase = 0;
    if (offsets) {
        int e = blockIdx.z;
        rowbase = offsets[e];
        M = min(counts[e], CAP);
        B += (size_t)e * Ntot * K;
    }
    int m0 = blockIdx.y * BM;
    if (m0 >= M) return;
    int n0 = blockIdx.x * BN;

    __shared__ unsigned As[BM][LDS];
    __shared__ unsigned Bs[BN][LDS];

    int tid  = threadIdx.x;
    int warp = tid >> 5, lane = tid & 31;
    int wm = warp >> 2, wn = warp & 3;       // 2 x 4 warp grid
    int mbase_w = wm * 64, nbase_w = wn * 32;
    int grp = lane >> 2, tig = lane & 3;

    // global load mapping: idx = i*256 + tid; row = idx>>3, c4 = idx&7 (float4 col)
    const float* aptr[4];
    const float* bptr[4];
    unsigned sArow[4], sAcol[4];
    #pragma unroll
    for (int i = 0; i < 4; i++) {
        int idx = i * 256 + tid;
        int row = idx >> 3, c4 = idx & 7;
        int ar = min(m0 + row, M - 1);
        int phys = rowmap ? rowmap[rowbase + ar] : (rowbase + ar);
        aptr[i] = A + (size_t)phys * lda + c4 * 4;
        bptr[i] = B + (size_t)(n0 + row) * K + c4 * 4;
        sArow[i] = row; sAcol[i] = c4 * 4;
    }

    float acc[4][4][4];
    #pragma unroll
    for (int mt = 0; mt < 4; mt++)
        #pragma unroll
        for (int nt = 0; nt < 4; nt++)
            #pragma unroll
            for (int j = 0; j < 4; j++) acc[mt][nt][j] = 0.f;

    float4 ra[4], rb[4];
    #pragma unroll
    for (int i = 0; i < 4; i++) { ra[i] = *(const float4*)aptr[i]; rb[i] = *(const float4*)bptr[i]; }

    for (int k0 = 0; k0 < K; k0 += BK) {
        // stage registers -> smem (cvt to tf32)
        #pragma unroll
        for (int i = 0; i < 4; i++) {
            uint4 ua = make_uint4(f2tf32(ra[i].x), f2tf32(ra[i].y), f2tf32(ra[i].z), f2tf32(ra[i].w));
            uint4 ub = make_uint4(f2tf32(rb[i].x), f2tf32(rb[i].y), f2tf32(rb[i].z), f2tf32(rb[i].w));
            *(uint4*)&As[sArow[i]][sAcol[i]] = ua;
            *(uint4*)&Bs[sArow[i]][sAcol[i]] = ub;
        }
        __syncthreads();

        // prefetch next k-tile
        if (k0 + BK < K) {
            #pragma unroll
            for (int i = 0; i < 4; i++) {
                ra[i] = *(const float4*)(aptr[i] + k0 + BK);
                rb[i] = *(const float4*)(bptr[i] + k0 + BK);
            }
        }

        // compute 4 k-steps of 8
        #pragma unroll
        for (int ks = 0; ks < 4; ks++) {
            int kq = ks * 8 + tig;
            unsigned af[4][4], bf[4][2];
            #pragma unroll
            for (int mt = 0; mt < 4; mt++) {
                int mr = mbase_w + mt * 16 + grp;
                af[mt][0] = As[mr][kq];
                af[mt][1] = As[mr + 8][kq];
                af[mt][2] = As[mr][kq + 4];
                af[mt][3] = As[mr + 8][kq + 4];
            }
            #pragma unroll
            for (int nt = 0; nt < 4; nt++) {
                int nr = nbase_w + nt * 8 + grp;
                bf[nt][0] = Bs[nr][kq];
                bf[nt][1] = Bs[nr][kq + 4];
            }
            #pragma unroll
            for (int mt = 0; mt < 4; mt++)
                #pragma unroll
                for (int nt = 0; nt < 4; nt++)
                    mma_tf32(acc[mt][nt], af[mt], bf[nt], acc[mt][nt]);
        }
        __syncthreads();
    }

    // epilogue
    #pragma unroll
    for (int mt = 0; mt < 4; mt++) {
        int row0 = m0 + mbase_w + mt * 16 + grp;
        #pragma unroll
        for (int nt = 0; nt < 4; nt++) {
            int col = n0 + nbase_w + nt * 8 + tig * 2;
            if (row0 < M) {
                float* p = C + (size_t)(rowbase + row0) * ldc + col;
                p[0] = acc[mt][nt][0]; p[1] = acc[mt][nt][1];
            }
            if (row0 + 8 < M) {
                float* p = C + (size_t)(rowbase + row0 + 8) * ldc + col;
                p[0] = acc[mt][nt][2]; p[1] = acc[mt][nt][3];
            }
        }
    }
}

// act = silu(g) * u, written into g
__global__ void swiglu_ew(float* __restrict__ g, const float* __restrict__ u, size_t n) {
    size_t i = (size_t)blockIdx.x * blockDim.x + threadIdx.x;
    if (i >= n) return;
    float gv = g[i];
    g[i] = (gv / (1.f + expf(-gv))) * u[i];
}

__global__ void combine_kernel(float* __restrict__ out) {
    int t = blockIdx.y;
    int d = blockIdx.x * blockDim.x + threadIdx.x;
    float s = out[(size_t)t * ND + d];
    #pragma unroll
    for (int k = 0; k < TOPK; k++) {
        int p = g_a2p[t * TOPK + k];
        if (p >= 0) s += g_tw[t * TOPK + k] * g_eo[(size_t)p * ND + d];
    }
    out[(size_t)t * ND + d] = s;
}

// ---------------- launch ----------------
extern "C" void kernel_launch(void* const* d_in, const int* in_sizes, int n_in,
                              void* d_out, int out_size)
{
    const float* x       = (const float*)d_in[0];
    const float* gate_w  = (const float*)d_in[1];
    const float* w_gate  = (const float*)d_in[2];
    const float* w_up    = (const float*)d_in[3];
    const float* w_down  = (const float*)d_in[4];
    const float* sh_gate = (const float*)d_in[5];
    const float* sh_up   = (const float*)d_in[6];
    const float* sh_down = (const float*)d_in[7];
    float* out = (float*)d_out;

    void *pg, *pu, *peo, *psg, *psu, *pstok, *poff, *pcnt;
    cudaGetSymbolAddress(&pg,   g_g);
    cudaGetSymbolAddress(&pu,   g_u);
    cudaGetSymbolAddress(&peo,  g_eo);
    cudaGetSymbolAddress(&psg,  g_sg);
    cudaGetSymbolAddress(&psu,  g_su);
    cudaGetSymbolAddress(&pstok, g_stok);
    cudaGetSymbolAddress(&poff, g_offsets);
    cudaGetSymbolAddress(&pcnt, g_counts);
    float* gbuf = (float*)pg;  float* ubuf = (float*)pu;  float* eo = (float*)peo;
    float* sg = (float*)psg;   float* su = (float*)psu;
    int* stok = (int*)pstok;   int* offs = (int*)poff;    int* cnts = (int*)pcnt;

    // 1) router + dispatch
    zero_kernel<<<1, 64>>>();
    router_kernel<<<NTOK, 256>>>(x, gate_w);
    prefix_kernel<<<1, 1>>>();
    scatter_kernel<<<(NA + 255) / 256, 256>>>();

    // 2) routed expert GEMMs
    {
        dim3 grid(NF / BN, CAP / BM, NE);
        gemm_tf32<<<grid, 256>>>(x, ND, w_gate, gbuf, NF, 0, NF, ND, stok, offs, cnts);
        gemm_tf32<<<grid, 256>>>(x, ND, w_up,   ubuf, NF, 0, NF, ND, stok, offs, cnts);
    }
    {
        size_t n = (size_t)NA * NF;
        swiglu_ew<<<(unsigned)((n + 255) / 256), 256>>>(gbuf, ubuf, n);
    }
    {
        dim3 grid(ND / BN, CAP / BM, NE);
        gemm_tf32<<<grid, 256>>>(gbuf, NF, w_down, eo, ND, 0, ND, NF, nullptr, offs, cnts);
    }

    // 3) shared expert (writes d_out directly)
    {
        dim3 grid(NFS / BN, NTOK / BM, 1);
        gemm_tf32<<<grid, 256>>>(x, ND, sh_gate, sg, NFS, NTOK, NFS, ND, nullptr, nullptr, nullptr);
        gemm_tf32<<<grid, 256>>>(x, ND, sh_up,   su, NFS, NTOK, NFS, ND, nullptr, nullptr, nullptr);
    }
    {
        size_t n = (size_t)NTOK * NFS;
        swiglu_ew<<<(unsigned)((n + 255) / 256), 256>>>(sg, su, n);
    }
    {
        dim3 grid(ND / BN, NTOK / BM, 1);
        gemm_tf32<<<grid, 256>>>(sg, NFS, sh_down, out, ND, NTOK, ND, NFS, nullptr, nullptr, nullptr);
    }

    // 4) combine routed outputs into d_out
    {
        dim3 grid(ND / 256, NTOK);
        combine_kernel<<<grid, 256>>>(out);
    }
}

// round 5
// speedup vs baseline: 3.1103x; 1.0065x over previous
#include <cuda_runtime.h>
#include <cstdint>
#include <math.h>

// ---------------- problem constants ----------------
#define TOPK 6
#define NE   64
#define ND   2048
#define NF   1408
#define NFS  2816
#define NTOK 8192
#define NA   (NTOK*TOPK)   // 49152 routed assignments
#define CAP  1536

// ---------------- scratch (device globals) ----------------
__device__ int   g_counts[NE];
__device__ int   g_offsets[NE];
__device__ int   g_cursor[NE];
__device__ int   g_tidx[NA];
__device__ float g_tw[NA];
__device__ int   g_stok[NA];
__device__ int   g_a2p[NA];
__device__ float g_g [(size_t)NA * NF];
__device__ float g_u [(size_t)NA * NF];
__device__ float g_eo[(size_t)NA * ND];
__device__ float g_sg[(size_t)NTOK * NFS];
__device__ float g_su[(size_t)NTOK * NFS];

// ---------------- small kernels ----------------
__global__ void zero_kernel() {
    int i = threadIdx.x;
    if (i < NE) { g_counts[i] = 0; g_cursor[i] = 0; }
}

__global__ void router_kernel(const float* __restrict__ x,
                              const float* __restrict__ gw)
{
    int t = blockIdx.x;
    __shared__ float xs[ND];
    __shared__ float logits[NE];
    const float* xr = x + (size_t)t * ND;
    for (int i = threadIdx.x; i < ND; i += blockDim.x) xs[i] = xr[i];
    __syncthreads();

    int warp = threadIdx.x >> 5, lane = threadIdx.x & 31;
    #pragma unroll
    for (int e8 = 0; e8 < 8; e8++) {
        int e = warp * 8 + e8;
        const float* w = gw + (size_t)e * ND;
        float s = 0.f;
        for (int i = lane; i < ND; i += 32) s += xs[i] * w[i];
        #pragma unroll
        for (int o = 16; o; o >>= 1) s += __shfl_down_sync(0xffffffffu, s, o);
        if (lane == 0) logits[e] = s;
    }
    __syncthreads();

    if (threadIdx.x == 0) {
        int idx6[TOPK]; float val6[TOPK];
        unsigned long long used = 0ull;
        for (int k = 0; k < TOPK; k++) {
            float best = -INFINITY; int bi = 0;
            for (int e = 0; e < NE; e++) {
                if (!((used >> e) & 1ull) && logits[e] > best) { best = logits[e]; bi = e; }
            }
            used |= 1ull << bi; idx6[k] = bi; val6[k] = best;
        }
        float m = val6[0], sum = 0.f, w6[TOPK];
        #pragma unroll
        for (int k = 0; k < TOPK; k++) { w6[k] = expf(val6[k] - m); sum += w6[k]; }
        float inv = 1.f / sum;
        #pragma unroll
        for (int k = 0; k < TOPK; k++) {
            g_tidx[t * TOPK + k] = idx6[k];
            g_tw  [t * TOPK + k] = w6[k] * inv;
            atomicAdd(&g_counts[idx6[k]], 1);
        }
    }
}

__global__ void prefix_kernel() {
    if (threadIdx.x == 0) {
        int acc = 0;
        for (int e = 0; e < NE; e++) { g_offsets[e] = acc; acc += g_counts[e]; }
    }
}

__global__ void scatter_kernel() {
    int a = blockIdx.x * blockDim.x + threadIdx.x;
    if (a >= NA) return;
    int e = g_tidx[a];
    int slot = atomicAdd(&g_cursor[e], 1);
    if (slot < CAP) {
        int p = g_offsets[e] + slot;
        g_stok[p] = a / TOPK;
        g_a2p[a] = p;
    } else {
        g_a2p[a] = -1;
    }
}

// ---------------- tf32 tensor-core GEMM (legacy mma.sync, double-buffered) ----
// C[m][n] = sum_k A[m][k] * B[n][k]  (both row-major, B is a weight [N][K])
// expert mode (offsets != null): e = blockIdx.z, rows at [offsets[e], +min(counts,CAP))
// gather mode (rowmap != null): physical A row = rowmap[rowbase + m]
#define BM 128
#define BN 128
#define BK 32
#define LDSW 36             // padded k-stride in words: conflict-free
#define STG_WORDS (BM * LDSW)          // words per matrix per stage (4608)
#define STAGE_STRIDE (2 * STG_WORDS)   // A + B per stage (9216 words)
#define SMEM_GEMM (2 * STAGE_STRIDE * 4)   // 73728 bytes

__device__ __forceinline__ unsigned f2tf32(float f) {
    unsigned u;
    asm volatile("cvt.rna.tf32.f32 %0, %1;" : "=r"(u) : "f"(f));
    return u;
}

__device__ __forceinline__ void mma_tf32(float d[4], const unsigned a[4],
                                         const unsigned b[2], const float c[4]) {
    asm volatile(
        "mma.sync.aligned.m16n8k8.row.col.f32.tf32.tf32.f32 "
        "{%0,%1,%2,%3},{%4,%5,%6,%7},{%8,%9},{%10,%11,%12,%13};\n"
        : "=f"(d[0]), "=f"(d[1]), "=f"(d[2]), "=f"(d[3])
        : "r"(a[0]), "r"(a[1]), "r"(a[2]), "r"(a[3]),
          "r"(b[0]), "r"(b[1]),
          "f"(c[0]), "f"(c[1]), "f"(c[2]), "f"(c[3]));
}

__global__ __launch_bounds__(256)
void gemm_tf32(const float* __restrict__ A, int lda,
               const float* __restrict__ B,
               float* __restrict__ C, int ldc,
               int M, int Ntot, int K,
               const int* __restrict__ rowmap,
               const int* __restrict__ offsets,
               const int* __restrict__ counts)
{
    extern __shared__ unsigned dsm[];
    int rowbase = 0;
    if (offsets) {
        int e = blockIdx.z;
        rowbase = offsets[e];
        M = min(counts[e], CAP);
        B += (size_t)e * Ntot * K;
    }
    int m0 = blockIdx.y * BM;
    if (m0 >= M) return;
    int n0 = blockIdx.x * BN;

    int tid  = threadIdx.x;
    int warp = tid >> 5, lane = tid & 31;
    int wm = warp >> 2, wn = warp & 3;       // 2 x 4 warp grid
    int mbase_w = wm * 64, nbase_w = wn * 32;
    int grp = lane >> 2, tig = lane & 3;

    // global load mapping: idx = i*256 + tid; row = idx>>3, c4 = idx&7 (float4 col)
    const float* aptr[4];
    const float* bptr[4];
    unsigned soff[4];   // word offset within a stage's matrix: row*LDSW + col
    #pragma unroll
    for (int i = 0; i < 4; i++) {
        int idx = i * 256 + tid;
        int row = idx >> 3, c4 = idx & 7;
        int ar = min(m0 + row, M - 1);
        int phys = rowmap ? rowmap[rowbase + ar] : (rowbase + ar);
        aptr[i] = A + (size_t)phys * lda + c4 * 4;
        bptr[i] = B + (size_t)(n0 + row) * K + c4 * 4;
        soff[i] = row * LDSW + c4 * 4;
    }

    float acc[4][4][4];
    #pragma unroll
    for (int mt = 0; mt < 4; mt++)
        #pragma unroll
        for (int nt = 0; nt < 4; nt++)
            #pragma unroll
            for (int j = 0; j < 4; j++) acc[mt][nt][j] = 0.f;

    const int nch = K / BK;
    float4 ra[4], rb[4];

    // prolog: load chunk 0, store to stage 0, load chunk 1
    #pragma unroll
    for (int i = 0; i < 4; i++) { ra[i] = *(const float4*)aptr[i]; rb[i] = *(const float4*)bptr[i]; }
    {
        unsigned* As0 = dsm;
        unsigned* Bs0 = dsm + STG_WORDS;
        #pragma unroll
        for (int i = 0; i < 4; i++) {
            *(uint4*)&As0[soff[i]] = make_uint4(f2tf32(ra[i].x), f2tf32(ra[i].y), f2tf32(ra[i].z), f2tf32(ra[i].w));
            *(uint4*)&Bs0[soff[i]] = make_uint4(f2tf32(rb[i].x), f2tf32(rb[i].y), f2tf32(rb[i].z), f2tf32(rb[i].w));
        }
    }
    if (nch > 1) {
        #pragma unroll
        for (int i = 0; i < 4; i++) {
            ra[i] = *(const float4*)(aptr[i] + BK);
            rb[i] = *(const float4*)(bptr[i] + BK);
        }
    }
    __syncthreads();

    for (int i = 0; i < nch; i++) {
        int s = i & 1;
        const unsigned* Asm = dsm + s * STAGE_STRIDE;
        const unsigned* Bsm = Asm + STG_WORDS;

        // fill the other stage with chunk i+1 (already in regs), prefetch i+2
        if (i + 1 < nch) {
            unsigned* Ad = dsm + (s ^ 1) * STAGE_STRIDE;
            unsigned* Bd = Ad + STG_WORDS;
            #pragma unroll
            for (int j = 0; j < 4; j++) {
                *(uint4*)&Ad[soff[j]] = make_uint4(f2tf32(ra[j].x), f2tf32(ra[j].y), f2tf32(ra[j].z), f2tf32(ra[j].w));
                *(uint4*)&Bd[soff[j]] = make_uint4(f2tf32(rb[j].x), f2tf32(rb[j].y), f2tf32(rb[j].z), f2tf32(rb[j].w));
            }
            if (i + 2 < nch) {
                const float* a2 = aptr[0] + (size_t)(i + 2) * BK;  // dummy init avoidance
                #pragma unroll
                for (int j = 0; j < 4; j++) {
                    ra[j] = *(const float4*)(aptr[j] + (size_t)(i + 2) * BK);
                    rb[j] = *(const float4*)(bptr[j] + (size_t)(i + 2) * BK);
                }
                (void)a2;
            }
        }

        // compute 4 k-steps of 8 on stage s
        #pragma unroll
        for (int ks = 0; ks < 4; ks++) {
            int kq = ks * 8 + tig;
            unsigned af[4][4], bf[4][2];
            #pragma unroll
            for (int mt = 0; mt < 4; mt++) {
                int mr = mbase_w + mt * 16 + grp;
                af[mt][0] = Asm[mr * LDSW + kq];
                af[mt][1] = Asm[(mr + 8) * LDSW + kq];
                af[mt][2] = Asm[mr * LDSW + kq + 4];
                af[mt][3] = Asm[(mr + 8) * LDSW + kq + 4];
            }
            #pragma unroll
            for (int nt = 0; nt < 4; nt++) {
                int nr = nbase_w + nt * 8 + grp;
                bf[nt][0] = Bsm[nr * LDSW + kq];
                bf[nt][1] = Bsm[nr * LDSW + kq + 4];
            }
            #pragma unroll
            for (int mt = 0; mt < 4; mt++)
                #pragma unroll
                for (int nt = 0; nt < 4; nt++)
                    mma_tf32(acc[mt][nt], af[mt], bf[nt], acc[mt][nt]);
        }
        __syncthreads();
    }

    // epilogue
    #pragma unroll
    for (int mt = 0; mt < 4; mt++) {
        int row0 = m0 + mbase_w + mt * 16 + grp;
        #pragma unroll
        for (int nt = 0; nt < 4; nt++) {
            int col = n0 + nbase_w + nt * 8 + tig * 2;
            if (row0 < M) {
                float* p = C + (size_t)(rowbase + row0) * ldc + col;
                p[0] = acc[mt][nt][0]; p[1] = acc[mt][nt][1];
            }
            if (row0 + 8 < M) {
                float* p = C + (size_t)(rowbase + row0 + 8) * ldc + col;
                p[0] = acc[mt][nt][2]; p[1] = acc[mt][nt][3];
            }
        }
    }
}

// act = silu(g) * u, written into g
__global__ void swiglu_ew(float* __restrict__ g, const float* __restrict__ u, size_t n) {
    size_t i = (size_t)blockIdx.x * blockDim.x + threadIdx.x;
    if (i >= n) return;
    float gv = g[i];
    g[i] = (gv / (1.f + expf(-gv))) * u[i];
}

__global__ void combine_kernel(float* __restrict__ out) {
    int t = blockIdx.y;
    int d = blockIdx.x * blockDim.x + threadIdx.x;
    float s = out[(size_t)t * ND + d];
    #pragma unroll
    for (int k = 0; k < TOPK; k++) {
        int p = g_a2p[t * TOPK + k];
        if (p >= 0) s += g_tw[t * TOPK + k] * g_eo[(size_t)p * ND + d];
    }
    out[(size_t)t * ND + d] = s;
}

// ---------------- launch ----------------
extern "C" void kernel_launch(void* const* d_in, const int* in_sizes, int n_in,
                              void* d_out, int out_size)
{
    const float* x       = (const float*)d_in[0];
    const float* gate_w  = (const float*)d_in[1];
    const float* w_gate  = (const float*)d_in[2];
    const float* w_up    = (const float*)d_in[3];
    const float* w_down  = (const float*)d_in[4];
    const float* sh_gate = (const float*)d_in[5];
    const float* sh_up   = (const float*)d_in[6];
    const float* sh_down = (const float*)d_in[7];
    float* out = (float*)d_out;

    void *pg, *pu, *peo, *psg, *psu, *pstok, *poff, *pcnt;
    cudaGetSymbolAddress(&pg,   g_g);
    cudaGetSymbolAddress(&pu,   g_u);
    cudaGetSymbolAddress(&peo,  g_eo);
    cudaGetSymbolAddress(&psg,  g_sg);
    cudaGetSymbolAddress(&psu,  g_su);
    cudaGetSymbolAddress(&pstok, g_stok);
    cudaGetSymbolAddress(&poff, g_offsets);
    cudaGetSymbolAddress(&pcnt, g_counts);
    float* gbuf = (float*)pg;  float* ubuf = (float*)pu;  float* eo = (float*)peo;
    float* sg = (float*)psg;   float* su = (float*)psu;
    int* stok = (int*)pstok;   int* offs = (int*)poff;    int* cnts = (int*)pcnt;

    cudaFuncSetAttribute(gemm_tf32, cudaFuncAttributeMaxDynamicSharedMemorySize, SMEM_GEMM);

    // 1) router + dispatch
    zero_kernel<<<1, 64>>>();
    router_kernel<<<NTOK, 256>>>(x, gate_w);
    prefix_kernel<<<1, 1>>>();
    scatter_kernel<<<(NA + 255) / 256, 256>>>();

    // 2) routed expert GEMMs
    {
        dim3 grid(NF / BN, CAP / BM, NE);
        gemm_tf32<<<grid, 256, SMEM_GEMM>>>(x, ND, w_gate, gbuf, NF, 0, NF, ND, stok, offs, cnts);
        gemm_tf32<<<grid, 256, SMEM_GEMM>>>(x, ND, w_up,   ubuf, NF, 0, NF, ND, stok, offs, cnts);
    }
    {
        size_t n = (size_t)NA * NF;
        swiglu_ew<<<(unsigned)((n + 255) / 256), 256>>>(gbuf, ubuf, n);
    }
    {
        dim3 grid(ND / BN, CAP / BM, NE);
        gemm_tf32<<<grid, 256, SMEM_GEMM>>>(gbuf, NF, w_down, eo, ND, 0, ND, NF, nullptr, offs, cnts);
    }

    // 3) shared expert (writes d_out directly)
    {
        dim3 grid(NFS / BN, NTOK / BM, 1);
        gemm_tf32<<<grid, 256, SMEM_GEMM>>>(x, ND, sh_gate, sg, NFS, NTOK, NFS, ND, nullptr, nullptr, nullptr);
        gemm_tf32<<<grid, 256, SMEM_GEMM>>>(x, ND, sh_up,   su, NFS, NTOK, NFS, ND, nullptr, nullptr, nullptr);
    }
    {
        size_t n = (size_t)NTOK * NFS;
        swiglu_ew<<<(unsigned)((n + 255) / 256), 256>>>(sg, su, n);
    }
    {
        dim3 grid(ND / BN, NTOK / BM, 1);
        gemm_tf32<<<grid, 256, SMEM_GEMM>>>(sg, NFS, sh_down, out, ND, NTOK, ND, NFS, nullptr, nullptr, nullptr);
    }

    // 4) combine routed outputs into d_out
    {
        dim3 grid(ND / 256, NTOK);
        combine_kernel<<<grid, 256>>>(out);
    }
}

// round 6
// speedup vs baseline: 3.5859x; 1.1529x over previous
#include <cuda_runtime.h>
#include <cstdint>
#include <math.h>

// ---------------- problem constants ----------------
#define TOPK 6
#define NE   64
#define ND   2048
#define NF   1408
#define NFS  2816
#define NTOK 8192
#define NA   (NTOK*TOPK)   // 49152 routed assignments
#define CAP  1536

// ---------------- scratch (device globals) ----------------
__device__ int   g_counts[NE];
__device__ int   g_offsets[NE];
__device__ int   g_cursor[NE];
__device__ int   g_tidx[NA];
__device__ float g_tw[NA];
__device__ int   g_stok[NA];
__device__ int   g_a2p[NA];
__device__ float g_u [(size_t)NA * NF];    // up proj, then act in place
__device__ float g_eo[(size_t)NA * ND];    // expert output rows
__device__ float g_su[(size_t)NTOK * NFS]; // shared up, then act in place

// ---------------- small kernels ----------------
__global__ void zero_kernel() {
    int i = threadIdx.x;
    if (i < NE) { g_counts[i] = 0; g_cursor[i] = 0; }
}

__global__ void router_kernel(const float* __restrict__ x,
                              const float* __restrict__ gw)
{
    int t = blockIdx.x;
    __shared__ float xs[ND];
    __shared__ float logits[NE];
    const float* xr = x + (size_t)t * ND;
    for (int i = threadIdx.x; i < ND; i += blockDim.x) xs[i] = xr[i];
    __syncthreads();

    int warp = threadIdx.x >> 5, lane = threadIdx.x & 31;
    #pragma unroll
    for (int e8 = 0; e8 < 8; e8++) {
        int e = warp * 8 + e8;
        const float* w = gw + (size_t)e * ND;
        float s = 0.f;
        for (int i = lane; i < ND; i += 32) s += xs[i] * w[i];
        #pragma unroll
        for (int o = 16; o; o >>= 1) s += __shfl_down_sync(0xffffffffu, s, o);
        if (lane == 0) logits[e] = s;
    }
    __syncthreads();

    if (threadIdx.x == 0) {
        int idx6[TOPK]; float val6[TOPK];
        unsigned long long used = 0ull;
        for (int k = 0; k < TOPK; k++) {
            float best = -INFINITY; int bi = 0;
            for (int e = 0; e < NE; e++) {
                if (!((used >> e) & 1ull) && logits[e] > best) { best = logits[e]; bi = e; }
            }
            used |= 1ull << bi; idx6[k] = bi; val6[k] = best;
        }
        float m = val6[0], sum = 0.f, w6[TOPK];
        #pragma unroll
        for (int k = 0; k < TOPK; k++) { w6[k] = expf(val6[k] - m); sum += w6[k]; }
        float inv = 1.f / sum;
        #pragma unroll
        for (int k = 0; k < TOPK; k++) {
            g_tidx[t * TOPK + k] = idx6[k];
            g_tw  [t * TOPK + k] = w6[k] * inv;
            atomicAdd(&g_counts[idx6[k]], 1);
        }
    }
}

__global__ void prefix_kernel() {
    if (threadIdx.x == 0) {
        int acc = 0;
        for (int e = 0; e < NE; e++) { g_offsets[e] = acc; acc += g_counts[e]; }
    }
}

__global__ void scatter_kernel() {
    int a = blockIdx.x * blockDim.x + threadIdx.x;
    if (a >= NA) return;
    int e = g_tidx[a];
    int slot = atomicAdd(&g_cursor[e], 1);
    if (slot < CAP) {
        int p = g_offsets[e] + slot;
        g_stok[p] = a / TOPK;
        g_a2p[a] = p;
    } else {
        g_a2p[a] = -1;
    }
}

// ---------------- tf32 tensor-core GEMM (legacy mma.sync) ----------------
// C[m][n] = sum_k A[m][k] * B[n][k]  (row-major; B is a weight [N][K])
// 128 threads, CTA tile 128x128, warp tile 64x64 (2x2 warps), BK=32,
// single smem stage, 2 CTAs/SM for cross-CTA overlap.
// mode 1: C[idx] = silu(acc) * C[idx]  (fused SwiGLU; C preloaded with "up")
#define BM 128
#define BN 128
#define BK 32
#define LDSW 36
#define STG_WORDS (BM * LDSW)          // 4608 words per matrix
#define SMEM_GEMM (2 * STG_WORDS * 4)  // 36864 bytes

__device__ __forceinline__ unsigned f2tf32(float f) {
    unsigned u;
    asm volatile("cvt.rna.tf32.f32 %0, %1;" : "=r"(u) : "f"(f));
    return u;
}

__device__ __forceinline__ void mma_tf32(float d[4], const unsigned a[4],
                                         const unsigned b[2], const float c[4]) {
    asm volatile(
        "mma.sync.aligned.m16n8k8.row.col.f32.tf32.tf32.f32 "
        "{%0,%1,%2,%3},{%4,%5,%6,%7},{%8,%9},{%10,%11,%12,%13};\n"
        : "=f"(d[0]), "=f"(d[1]), "=f"(d[2]), "=f"(d[3])
        : "r"(a[0]), "r"(a[1]), "r"(a[2]), "r"(a[3]),
          "r"(b[0]), "r"(b[1]),
          "f"(c[0]), "f"(c[1]), "f"(c[2]), "f"(c[3]));
}

__global__ __launch_bounds__(128)
void gemm_tf32(const float* __restrict__ A, int lda,
               const float* __restrict__ B,
               float* __restrict__ C, int ldc,
               int M, int Ntot, int K, int mode,
               const int* __restrict__ rowmap,
               const int* __restrict__ offsets,
               const int* __restrict__ counts)
{
    extern __shared__ unsigned dsm[];
    int rowbase = 0;
    if (offsets) {
        int e = blockIdx.z;
        rowbase = offsets[e];
        M = min(counts[e], CAP);
        B += (size_t)e * Ntot * K;
    }
    int m0 = blockIdx.y * BM;
    if (m0 >= M) return;
    int n0 = blockIdx.x * BN;

    unsigned* As = dsm;
    unsigned* Bs = dsm + STG_WORDS;

    int tid  = threadIdx.x;
    int warp = tid >> 5, lane = tid & 31;
    int wm = warp >> 1, wn = warp & 1;       // 2 x 2 warp grid
    int mbase_w = wm * 64, nbase_w = wn * 64;
    int grp = lane >> 2, tig = lane & 3;

    // fill mapping: per thread 8 rows (stride 16) x one float4 column
    int c4 = (tid & 7) * 4;
    int r0 = tid >> 3;                        // 0..15
    int aphys[8];
    #pragma unroll
    for (int i = 0; i < 8; i++) {
        int ar = min(m0 + r0 + 16 * i, M - 1);
        aphys[i] = rowmap ? rowmap[rowbase + ar] : (rowbase + ar);
    }
    const float* b0 = B + (size_t)(n0 + r0) * K + c4;
    unsigned soff0 = r0 * LDSW + c4;

    float acc[4][8][4];
    #pragma unroll
    for (int mt = 0; mt < 4; mt++)
        #pragma unroll
        for (int nt = 0; nt < 8; nt++)
            #pragma unroll
            for (int j = 0; j < 4; j++) acc[mt][nt][j] = 0.f;

    for (int k0 = 0; k0 < K; k0 += BK) {
        // fill stage
        #pragma unroll
        for (int i = 0; i < 8; i++) {
            float4 av = *(const float4*)(A + (size_t)aphys[i] * lda + c4 + k0);
            float4 bv = *(const float4*)(b0 + (size_t)(16 * i) * K + k0);
            *(uint4*)&As[soff0 + i * 16 * LDSW] =
                make_uint4(f2tf32(av.x), f2tf32(av.y), f2tf32(av.z), f2tf32(av.w));
            *(uint4*)&Bs[soff0 + i * 16 * LDSW] =
                make_uint4(f2tf32(bv.x), f2tf32(bv.y), f2tf32(bv.z), f2tf32(bv.w));
        }
        __syncthreads();

        // compute 4 k-steps of 8
        #pragma unroll
        for (int ks = 0; ks < 4; ks++) {
            int kq = ks * 8 + tig;
            unsigned af[4][4], bf[8][2];
            #pragma unroll
            for (int mt = 0; mt < 4; mt++) {
                int mr = mbase_w + mt * 16 + grp;
                af[mt][0] = As[mr * LDSW + kq];
                af[mt][1] = As[(mr + 8) * LDSW + kq];
                af[mt][2] = As[mr * LDSW + kq + 4];
                af[mt][3] = As[(mr + 8) * LDSW + kq + 4];
            }
            #pragma unroll
            for (int nt = 0; nt < 8; nt++) {
                int nr = nbase_w + nt * 8 + grp;
                bf[nt][0] = Bs[nr * LDSW + kq];
                bf[nt][1] = Bs[nr * LDSW + kq + 4];
            }
            #pragma unroll
            for (int mt = 0; mt < 4; mt++)
                #pragma unroll
                for (int nt = 0; nt < 8; nt++)
                    mma_tf32(acc[mt][nt], af[mt], bf[nt], acc[mt][nt]);
        }
        __syncthreads();
    }

    // epilogue
    #pragma unroll
    for (int mt = 0; mt < 4; mt++) {
        int row0 = m0 + mbase_w + mt * 16 + grp;
        #pragma unroll
        for (int nt = 0; nt < 8; nt++) {
            int col = n0 + nbase_w + nt * 8 + tig * 2;
            if (row0 < M) {
                float* p = C + (size_t)(rowbase + row0) * ldc + col;
                float v0 = acc[mt][nt][0], v1 = acc[mt][nt][1];
                if (mode) {
                    v0 = (v0 / (1.f + expf(-v0))) * p[0];
                    v1 = (v1 / (1.f + expf(-v1))) * p[1];
                }
                p[0] = v0; p[1] = v1;
            }
            if (row0 + 8 < M) {
                float* p = C + (size_t)(rowbase + row0 + 8) * ldc + col;
                float v0 = acc[mt][nt][2], v1 = acc[mt][nt][3];
                if (mode) {
                    v0 = (v0 / (1.f + expf(-v0))) * p[0];
                    v1 = (v1 / (1.f + expf(-v1))) * p[1];
                }
                p[0] = v0; p[1] = v1;
            }
        }
    }
}

// out[t][d] += sum_k w(t,k) * eo[pos(t,k)][d]
__global__ void combine_kernel(float* __restrict__ out) {
    int t = blockIdx.y;
    int d = blockIdx.x * blockDim.x + threadIdx.x;
    float s = out[(size_t)t * ND + d];
    #pragma unroll
    for (int k = 0; k < TOPK; k++) {
        int p = g_a2p[t * TOPK + k];
        if (p >= 0) s += g_tw[t * TOPK + k] * g_eo[(size_t)p * ND + d];
    }
    out[(size_t)t * ND + d] = s;
}

// ---------------- launch ----------------
extern "C" void kernel_launch(void* const* d_in, const int* in_sizes, int n_in,
                              void* d_out, int out_size)
{
    const float* x       = (const float*)d_in[0];
    const float* gate_w  = (const float*)d_in[1];
    const float* w_gate  = (const float*)d_in[2];
    const float* w_up    = (const float*)d_in[3];
    const float* w_down  = (const float*)d_in[4];
    const float* sh_gate = (const float*)d_in[5];
    const float* sh_up   = (const float*)d_in[6];
    const float* sh_down = (const float*)d_in[7];
    float* out = (float*)d_out;

    void *pu, *peo, *psu, *pstok, *poff, *pcnt;
    cudaGetSymbolAddress(&pu,   g_u);
    cudaGetSymbolAddress(&peo,  g_eo);
    cudaGetSymbolAddress(&psu,  g_su);
    cudaGetSymbolAddress(&pstok, g_stok);
    cudaGetSymbolAddress(&poff, g_offsets);
    cudaGetSymbolAddress(&pcnt, g_counts);
    float* ubuf = (float*)pu;  float* eo = (float*)peo;  float* su = (float*)psu;
    int* stok = (int*)pstok;   int* offs = (int*)poff;   int* cnts = (int*)pcnt;

    cudaFuncSetAttribute(gemm_tf32, cudaFuncAttributeMaxDynamicSharedMemorySize, SMEM_GEMM);

    // 1) router + dispatch
    zero_kernel<<<1, 64>>>();
    router_kernel<<<NTOK, 256>>>(x, gate_w);
    prefix_kernel<<<1, 1>>>();
    scatter_kernel<<<(NA + 255) / 256, 256>>>();

    // 2) routed experts: up -> ubuf; gate (fused silu*u) -> ubuf; down -> eo
    {
        dim3 grid(NF / BN, CAP / BM, NE);
        gemm_tf32<<<grid, 128, SMEM_GEMM>>>(x, ND, w_up,   ubuf, NF, 0, NF, ND, 0, stok, offs, cnts);
        gemm_tf32<<<grid, 128, SMEM_GEMM>>>(x, ND, w_gate, ubuf, NF, 0, NF, ND, 1, stok, offs, cnts);
    }
    {
        dim3 grid(ND / BN, CAP / BM, NE);
        gemm_tf32<<<grid, 128, SMEM_GEMM>>>(ubuf, NF, w_down, eo, ND, 0, ND, NF, 0, nullptr, offs, cnts);
    }

    // 3) shared expert: up -> su; gate (fused) -> su; down -> out
    {
        dim3 grid(NFS / BN, NTOK / BM, 1);
        gemm_tf32<<<grid, 128, SMEM_GEMM>>>(x, ND, sh_up,   su, NFS, NTOK, NFS, ND, 0, nullptr, nullptr, nullptr);
        gemm_tf32<<<grid, 128, SMEM_GEMM>>>(x, ND, sh_gate, su, NFS, NTOK, NFS, ND, 1, nullptr, nullptr, nullptr);
    }
    {
        dim3 grid(ND / BN, NTOK / BM, 1);
        gemm_tf32<<<grid, 128, SMEM_GEMM>>>(su, NFS, sh_down, out, ND, NTOK, ND, NFS, 0, nullptr, nullptr, nullptr);
    }

    // 4) combine routed outputs into d_out
    {
        dim3 grid(ND / 256, NTOK);
        combine_kernel<<<grid, 256>>>(out);
    }
}

// round 7
// speedup vs baseline: 4.4496x; 1.2409x over previous
#include <cuda_runtime.h>
#include <cuda_fp16.h>
#include <cstdint>
#include <math.h>

// ---------------- problem constants ----------------
#define TOPK 6
#define NE   64
#define ND   2048
#define NF   1408
#define NFS  2816
#define NTOK 8192
#define NA   (NTOK*TOPK)   // 49152 routed assignments
#define CAP  1536

// ---------------- scratch (device globals) ----------------
__device__ int    g_counts[NE];
__device__ int    g_offsets[NE];
__device__ int    g_cursor[NE];
__device__ int    g_tidx[NA];
__device__ float  g_tw[NA];
__device__ int    g_stok[NA];
__device__ int    g_a2p[NA];
__device__ __half g_u [(size_t)NA * NF];    // up proj then act, fp16
__device__ float  g_eo[(size_t)NA * ND];    // expert output rows
__device__ __half g_su[(size_t)NTOK * NFS]; // shared up then act, fp16

// ---------------- small kernels ----------------
__global__ void zero_kernel() {
    int i = threadIdx.x;
    if (i < NE) { g_counts[i] = 0; g_cursor[i] = 0; }
}

__global__ void router_kernel(const float* __restrict__ x,
                              const float* __restrict__ gw)
{
    int t = blockIdx.x;
    __shared__ float xs[ND];
    __shared__ float logits[NE];
    const float* xr = x + (size_t)t * ND;
    for (int i = threadIdx.x; i < ND; i += blockDim.x) xs[i] = xr[i];
    __syncthreads();

    int warp = threadIdx.x >> 5, lane = threadIdx.x & 31;
    #pragma unroll
    for (int e8 = 0; e8 < 8; e8++) {
        int e = warp * 8 + e8;
        const float* w = gw + (size_t)e * ND;
        float s = 0.f;
        for (int i = lane; i < ND; i += 32) s += xs[i] * w[i];
        #pragma unroll
        for (int o = 16; o; o >>= 1) s += __shfl_down_sync(0xffffffffu, s, o);
        if (lane == 0) logits[e] = s;
    }
    __syncthreads();

    if (threadIdx.x == 0) {
        int idx6[TOPK]; float val6[TOPK];
        unsigned long long used = 0ull;
        for (int k = 0; k < TOPK; k++) {
            float best = -INFINITY; int bi = 0;
            for (int e = 0; e < NE; e++) {
                if (!((used >> e) & 1ull) && logits[e] > best) { best = logits[e]; bi = e; }
            }
            used |= 1ull << bi; idx6[k] = bi; val6[k] = best;
        }
        float m = val6[0], sum = 0.f, w6[TOPK];
        #pragma unroll
        for (int k = 0; k < TOPK; k++) { w6[k] = expf(val6[k] - m); sum += w6[k]; }
        float inv = 1.f / sum;
        #pragma unroll
        for (int k = 0; k < TOPK; k++) {
            g_tidx[t * TOPK + k] = idx6[k];
            g_tw  [t * TOPK + k] = w6[k] * inv;
            atomicAdd(&g_counts[idx6[k]], 1);
        }
    }
}

__global__ void prefix_kernel() {
    if (threadIdx.x == 0) {
        int acc = 0;
        for (int e = 0; e < NE; e++) { g_offsets[e] = acc; acc += g_counts[e]; }
    }
}

__global__ void scatter_kernel() {
    int a = blockIdx.x * blockDim.x + threadIdx.x;
    if (a >= NA) return;
    int e = g_tidx[a];
    int slot = atomicAdd(&g_cursor[e], 1);
    if (slot < CAP) {
        int p = g_offsets[e] + slot;
        g_stok[p] = a / TOPK;
        g_a2p[a] = p;
    } else {
        g_a2p[a] = -1;
    }
}

// ---------------- fp16 tensor-core GEMM (mma.sync.m16n8k16) ----------------
// C[m][n] = sum_k A[m][k] * B[n][k]  (row-major; B is a weight [N][K] fp32)
// 128 threads, CTA tile 128x128, warp tile 64x64 (2x2 warps), BK=32.
// AH: A is fp16 buffer (no convert). OH: C is fp16. FUSE: C = silu(acc)*C (fp16).
#define LDSW16 20   // words per row (16 data + 4 pad) — conflict-free frags

__device__ __forceinline__ unsigned pack2(float a, float b) {
    __half2 h = __floats2half2_rn(a, b);
    return *(unsigned*)&h;
}

__device__ __forceinline__ void mma_f16(float d[4], const unsigned a[4],
                                        const unsigned b[2], const float c[4]) {
    asm volatile(
        "mma.sync.aligned.m16n8k16.row.col.f32.f16.f16.f32 "
        "{%0,%1,%2,%3},{%4,%5,%6,%7},{%8,%9},{%10,%11,%12,%13};\n"
        : "=f"(d[0]), "=f"(d[1]), "=f"(d[2]), "=f"(d[3])
        : "r"(a[0]), "r"(a[1]), "r"(a[2]), "r"(a[3]),
          "r"(b[0]), "r"(b[1]),
          "f"(c[0]), "f"(c[1]), "f"(c[2]), "f"(c[3]));
}

template<int AH, int OH, int FUSE>
__global__ __launch_bounds__(128)
void gemm16(const void* __restrict__ Av, int lda,
            const float* __restrict__ B,
            void* __restrict__ Cv, int ldc,
            int M, int Ntot, int K,
            const int* __restrict__ rowmap,
            const int* __restrict__ offsets,
            const int* __restrict__ counts)
{
    __shared__ unsigned As[128 * LDSW16];
    __shared__ unsigned Bs[128 * LDSW16];

    int rowbase = 0;
    if (offsets) {
        int e = blockIdx.z;
        rowbase = offsets[e];
        M = min(counts[e], CAP);
        B += (size_t)e * Ntot * K;
    }
    int m0 = blockIdx.y * 128;
    if (m0 >= M) return;
    int n0 = blockIdx.x * 128;

    int tid = threadIdx.x, warp = tid >> 5, lane = tid & 31;
    int wm = warp >> 1, wn = warp & 1;       // 2x2 warp grid
    int mb = wm * 64, nb = wn * 64;
    int grp = lane >> 2, tig = lane & 3;

    // fill mapping: thread covers row r0+32i, halves acol..acol+7
    int r0 = tid >> 2, q = tid & 3;
    int acol = q * 8;
    int aphys[4];
    const float* bp[4];
    #pragma unroll
    for (int i = 0; i < 4; i++) {
        int ar = min(m0 + r0 + 32 * i, M - 1);
        aphys[i] = rowmap ? rowmap[rowbase + ar] : (rowbase + ar);
        bp[i] = B + (size_t)(n0 + r0 + 32 * i) * K + acol;
    }
    unsigned so = r0 * LDSW16 + q * 4;

    float acc[4][8][4];
    #pragma unroll
    for (int mt = 0; mt < 4; mt++)
        #pragma unroll
        for (int nt = 0; nt < 8; nt++)
            #pragma unroll
            for (int j = 0; j < 4; j++) acc[mt][nt][j] = 0.f;

    for (int k0 = 0; k0 < K; k0 += 32) {
        // ---- fill stage ----
        #pragma unroll
        for (int i = 0; i < 4; i++) {
            unsigned off = so + i * 32 * LDSW16;
            if (AH) {
                const __half* Ah = ((const __half*)Av) + (size_t)aphys[i] * lda + k0 + acol;
                *(uint4*)&As[off] = *(const uint4*)Ah;
            } else {
                const float* Af = ((const float*)Av) + (size_t)aphys[i] * lda + k0 + acol;
                float4 f0 = *(const float4*)Af;
                float4 f1 = *(const float4*)(Af + 4);
                *(uint4*)&As[off] = make_uint4(pack2(f0.x, f0.y), pack2(f0.z, f0.w),
                                               pack2(f1.x, f1.y), pack2(f1.z, f1.w));
            }
            float4 g0 = *(const float4*)(bp[i] + k0);
            float4 g1 = *(const float4*)(bp[i] + k0 + 4);
            *(uint4*)&Bs[off] = make_uint4(pack2(g0.x, g0.y), pack2(g0.z, g0.w),
                                           pack2(g1.x, g1.y), pack2(g1.z, g1.w));
        }
        __syncthreads();

        // ---- compute: 2 k-steps of k16 ----
        #pragma unroll
        for (int ks = 0; ks < 2; ks++) {
            int kw = ks * 8 + tig;
            unsigned af[4][4], bf[8][2];
            #pragma unroll
            for (int mt = 0; mt < 4; mt++) {
                int mr = mb + mt * 16 + grp;
                af[mt][0] = As[mr * LDSW16 + kw];
                af[mt][1] = As[(mr + 8) * LDSW16 + kw];
                af[mt][2] = As[mr * LDSW16 + kw + 4];
                af[mt][3] = As[(mr + 8) * LDSW16 + kw + 4];
            }
            #pragma unroll
            for (int nt = 0; nt < 8; nt++) {
                int nr = nb + nt * 8 + grp;
                bf[nt][0] = Bs[nr * LDSW16 + kw];
                bf[nt][1] = Bs[nr * LDSW16 + kw + 4];
            }
            #pragma unroll
            for (int mt = 0; mt < 4; mt++)
                #pragma unroll
                for (int nt = 0; nt < 8; nt++)
                    mma_f16(acc[mt][nt], af[mt], bf[nt], acc[mt][nt]);
        }
        __syncthreads();
    }

    // ---- epilogue ----
    #pragma unroll
    for (int mt = 0; mt < 4; mt++) {
        int row0 = m0 + mb + mt * 16 + grp;
        #pragma unroll
        for (int nt = 0; nt < 8; nt++) {
            int col = n0 + nb + nt * 8 + tig * 2;
            #pragma unroll
            for (int h = 0; h < 2; h++) {
                int row = row0 + h * 8;
                if (row >= M) continue;
                float v0 = acc[mt][nt][2 * h], v1 = acc[mt][nt][2 * h + 1];
                if (OH) {
                    __half2* p = (__half2*)(((__half*)Cv) + (size_t)(rowbase + row) * ldc + col);
                    if (FUSE) {
                        float2 u = __half22float2(*p);
                        v0 = (v0 / (1.f + __expf(-v0))) * u.x;
                        v1 = (v1 / (1.f + __expf(-v1))) * u.y;
                    }
                    *p = __floats2half2_rn(v0, v1);
                } else {
                    float* p = ((float*)Cv) + (size_t)(rowbase + row) * ldc + col;
                    p[0] = v0; p[1] = v1;
                }
            }
        }
    }
}

// out[t][d] += sum_k w(t,k) * eo[pos(t,k)][d]
__global__ void combine_kernel(float* __restrict__ out) {
    int t = blockIdx.y;
    int d = blockIdx.x * blockDim.x + threadIdx.x;
    float s = out[(size_t)t * ND + d];
    #pragma unroll
    for (int k = 0; k < TOPK; k++) {
        int p = g_a2p[t * TOPK + k];
        if (p >= 0) s += g_tw[t * TOPK + k] * g_eo[(size_t)p * ND + d];
    }
    out[(size_t)t * ND + d] = s;
}

// ---------------- launch ----------------
extern "C" void kernel_launch(void* const* d_in, const int* in_sizes, int n_in,
                              void* d_out, int out_size)
{
    const float* x       = (const float*)d_in[0];
    const float* gate_w  = (const float*)d_in[1];
    const float* w_gate  = (const float*)d_in[2];
    const float* w_up    = (const float*)d_in[3];
    const float* w_down  = (const float*)d_in[4];
    const float* sh_gate = (const float*)d_in[5];
    const float* sh_up   = (const float*)d_in[6];
    const float* sh_down = (const float*)d_in[7];
    float* out = (float*)d_out;

    void *pu, *peo, *psu, *pstok, *poff, *pcnt;
    cudaGetSymbolAddress(&pu,   g_u);
    cudaGetSymbolAddress(&peo,  g_eo);
    cudaGetSymbolAddress(&psu,  g_su);
    cudaGetSymbolAddress(&pstok, g_stok);
    cudaGetSymbolAddress(&poff, g_offsets);
    cudaGetSymbolAddress(&pcnt, g_counts);
    __half* ubuf = (__half*)pu;  float* eo = (float*)peo;  __half* su = (__half*)psu;
    int* stok = (int*)pstok;     int* offs = (int*)poff;   int* cnts = (int*)pcnt;

    // 1) router + dispatch
    zero_kernel<<<1, 64>>>();
    router_kernel<<<NTOK, 256>>>(x, gate_w);
    prefix_kernel<<<1, 1>>>();
    scatter_kernel<<<(NA + 255) / 256, 256>>>();

    // 2) routed experts: up -> ubuf(fp16); gate fused silu*u -> ubuf; down -> eo(fp32)
    {
        dim3 grid(NF / 128, CAP / 128, NE);
        gemm16<0,1,0><<<grid, 128>>>(x, ND, w_up,   ubuf, NF, 0, NF, ND, stok, offs, cnts);
        gemm16<0,1,1><<<grid, 128>>>(x, ND, w_gate, ubuf, NF, 0, NF, ND, stok, offs, cnts);
    }
    {
        dim3 grid(ND / 128, CAP / 128, NE);
        gemm16<1,0,0><<<grid, 128>>>(ubuf, NF, w_down, eo, ND, 0, ND, NF, nullptr, offs, cnts);
    }

    // 3) shared expert: up -> su(fp16); gate fused -> su; down -> out(fp32)
    {
        dim3 grid(NFS / 128, NTOK / 128, 1);
        gemm16<0,1,0><<<grid, 128>>>(x, ND, sh_up,   su, NFS, NTOK, NFS, ND, nullptr, nullptr, nullptr);
        gemm16<0,1,1><<<grid, 128>>>(x, ND, sh_gate, su, NFS, NTOK, NFS, ND, nullptr, nullptr, nullptr);
    }
    {
        dim3 grid(ND / 128, NTOK / 128, 1);
        gemm16<1,0,0><<<grid, 128>>>(su, NFS, sh_down, out, ND, NTOK, ND, NFS, nullptr, nullptr, nullptr);
    }

    // 4) combine routed outputs into d_out
    {
        dim3 grid(ND / 256, NTOK);
        combine_kernel<<<grid, 256>>>(out);
    }
}

// round 9
// speedup vs baseline: 6.1684x; 1.3863x over previous
#include <cuda_runtime.h>
#include <cuda_fp16.h>
#include <cstdint>
#include <math.h>

// ---------------- problem constants ----------------
#define TOPK 6
#define NE   64
#define ND   2048
#define NF   1408
#define NFS  2816
#define NTOK 8192
#define NA   (NTOK*TOPK)   // 49152 routed assignments
#define CAP  1536

// ---------------- scratch (device globals) ----------------
__device__ int    g_counts[NE];
__device__ int    g_offsets[NE];
__device__ int    g_cursor[NE];
__device__ int    g_tidx[NA];
__device__ float  g_tw[NA];
__device__ int    g_stok[NA];
__device__ int    g_a2p[NA];
__device__ __half g_u [(size_t)NA * NF];    // up proj then act, fp16
__device__ float  g_eo[(size_t)NA * ND];    // expert output rows
__device__ __half g_su[(size_t)NTOK * NFS]; // shared up then act, fp16

// ---------------- small kernels ----------------
__global__ void zero_kernel() {
    int i = threadIdx.x;
    if (i < NE) { g_counts[i] = 0; g_cursor[i] = 0; }
}

__global__ void router_kernel(const float* __restrict__ x,
                              const float* __restrict__ gw)
{
    int t = blockIdx.x;
    __shared__ float xs[ND];
    __shared__ float logits[NE];
    const float* xr = x + (size_t)t * ND;
    for (int i = threadIdx.x; i < ND; i += blockDim.x) xs[i] = xr[i];
    __syncthreads();

    int warp = threadIdx.x >> 5, lane = threadIdx.x & 31;
    #pragma unroll
    for (int e8 = 0; e8 < 8; e8++) {
        int e = warp * 8 + e8;
        const float* w = gw + (size_t)e * ND;
        float s = 0.f;
        for (int i = lane; i < ND; i += 32) s += xs[i] * w[i];
        #pragma unroll
        for (int o = 16; o; o >>= 1) s += __shfl_down_sync(0xffffffffu, s, o);
        if (lane == 0) logits[e] = s;
    }
    __syncthreads();

    if (threadIdx.x == 0) {
        int idx6[TOPK]; float val6[TOPK];
        unsigned long long used = 0ull;
        for (int k = 0; k < TOPK; k++) {
            float best = -INFINITY; int bi = 0;
            for (int e = 0; e < NE; e++) {
                if (!((used >> e) & 1ull) && logits[e] > best) { best = logits[e]; bi = e; }
            }
            used |= 1ull << bi; idx6[k] = bi; val6[k] = best;
        }
        float m = val6[0], sum = 0.f, w6[TOPK];
        #pragma unroll
        for (int k = 0; k < TOPK; k++) { w6[k] = expf(val6[k] - m); sum += w6[k]; }
        float inv = 1.f / sum;
        #pragma unroll
        for (int k = 0; k < TOPK; k++) {
            g_tidx[t * TOPK + k] = idx6[k];
            g_tw  [t * TOPK + k] = w6[k] * inv;
            atomicAdd(&g_counts[idx6[k]], 1);
        }
    }
}

__global__ void prefix_kernel() {
    if (threadIdx.x == 0) {
        int acc = 0;
        for (int e = 0; e < NE; e++) { g_offsets[e] = acc; acc += g_counts[e]; }
    }
}

__global__ void scatter_kernel() {
    int a = blockIdx.x * blockDim.x + threadIdx.x;
    if (a >= NA) return;
    int e = g_tidx[a];
    int slot = atomicAdd(&g_cursor[e], 1);
    if (slot < CAP) {
        int p = g_offsets[e] + slot;
        g_stok[p] = a / TOPK;
        g_a2p[a] = p;
    } else {
        g_a2p[a] = -1;
    }
}

// ---------------- fp16 tensor-core GEMM v2 ----------------
// C[m][n] = sum_k A[m][k] * B[n][k]; 128 threads, CTA 128x128, warp 64x64,
// BK=32, 2 smem stages, register-staged prefetch, ldmatrix frag loads.
// Swizzled smem: 128 rows x 64B per matrix; conflict-free STS.128 + LDSM.

__device__ __forceinline__ uint32_t smem_u32(const void* p) {
    uint32_t a;
    asm("{ .reg .u64 t; cvta.to.shared.u64 t, %1; cvt.u32.u64 %0, t; }" : "=r"(a) : "l"(p));
    return a;
}

// byte offset of (row, h) where h = 16B column index (0..3) in a 128x64B matrix
__device__ __forceinline__ uint32_t swoff(int row, int h) {
    return (uint32_t)(((row >> 1) << 7) +
                      ((((h + ((row & 1) << 2)) ^ ((row >> 1) & 7))) << 4));
}

__device__ __forceinline__ unsigned pack2(float a, float b) {
    __half2 h = __floats2half2_rn(a, b);
    return *(unsigned*)&h;
}

__device__ __forceinline__ void ldsm4(unsigned& r0, unsigned& r1, unsigned& r2,
                                      unsigned& r3, uint32_t addr) {
    asm volatile("ldmatrix.sync.aligned.m8n8.x4.shared.b16 {%0,%1,%2,%3}, [%4];"
                 : "=r"(r0), "=r"(r1), "=r"(r2), "=r"(r3) : "r"(addr));
}

__device__ __forceinline__ void mma_f16(float d[4], const unsigned a[4],
                                        const unsigned b[2], const float c[4]) {
    asm volatile(
        "mma.sync.aligned.m16n8k16.row.col.f32.f16.f16.f32 "
        "{%0,%1,%2,%3},{%4,%5,%6,%7},{%8,%9},{%10,%11,%12,%13};\n"
        : "=f"(d[0]), "=f"(d[1]), "=f"(d[2]), "=f"(d[3])
        : "r"(a[0]), "r"(a[1]), "r"(a[2]), "r"(a[3]),
          "r"(b[0]), "r"(b[1]),
          "f"(c[0]), "f"(c[1]), "f"(c[2]), "f"(c[3]));
}

#define MAT_BYTES   8192            // 128 rows x 64B
#define STAGE_BYTES 16384           // A + B

template<int AH, int OH, int FUSE>
__global__ __launch_bounds__(128)
void gemm16(const void* __restrict__ Av, int lda,
            const float* __restrict__ B,
            void* __restrict__ Cv, int ldc,
            int M, int Ntot, int K,
            const int* __restrict__ rowmap,
            const int* __restrict__ offsets,
            const int* __restrict__ counts)
{
    __shared__ char sm[2 * STAGE_BYTES];

    int rowbase = 0;
    if (offsets) {
        int e = blockIdx.z;
        rowbase = offsets[e];
        M = min(counts[e], CAP);
        B += (size_t)e * Ntot * K;
    }
    int m0 = blockIdx.y * 128;
    if (m0 >= M) return;
    int n0 = blockIdx.x * 128;

    int tid = threadIdx.x, warp = tid >> 5, lane = tid & 31;
    int wm = warp >> 1, wn = warp & 1;
    int mb = wm * 64, nb = wn * 64;
    int grp = lane >> 2, tig = lane & 3;

    // ---- fill mapping: thread (r0 = tid>>2, q = tid&3) covers rows r0+32i ----
    int r0 = tid >> 2, q = tid & 3;
    int q8 = q * 8;
    int aphys[4];
    const float* bp[4];
    uint32_t stoff[4];
    #pragma unroll
    for (int i = 0; i < 4; i++) {
        int row = r0 + 32 * i;
        int ar = min(m0 + row, M - 1);
        aphys[i] = rowmap ? rowmap[rowbase + ar] : (rowbase + ar);
        bp[i] = B + (size_t)(n0 + row) * K + q8;
        stoff[i] = swoff(row, q);
    }

    // ---- ldmatrix lane mapping ----
    int lrow = (lane & 7) + 8 * ((lane >> 3) & 1);
    int lh = (lane >> 4) & 1;
    uint32_t sbase = smem_u32(sm);
    uint32_t aoff[2] = { swoff(mb + lrow, lh), swoff(mb + lrow, 2 + lh) };
    uint32_t boff[2] = { swoff(nb + lrow, lh), swoff(nb + lrow, 2 + lh) };

    float acc[4][8][4];
    #pragma unroll
    for (int mt = 0; mt < 4; mt++)
        #pragma unroll
        for (int nt = 0; nt < 8; nt++)
            #pragma unroll
            for (int j = 0; j < 4; j++) acc[mt][nt][j] = 0.f;

    // staging registers
    uint4 rah[4];          // AH=1
    float4 raf[4][2];      // AH=0
    float4 rbf[4][2];

    const int nch = K / 32;

    auto load_chunk = [&](int kc) {
        #pragma unroll
        for (int i = 0; i < 4; i++) {
            if (AH) {
                const __half* Ah = ((const __half*)Av) + (size_t)aphys[i] * lda + kc + q8;
                rah[i] = *(const uint4*)Ah;
            } else {
                const float* Af = ((const float*)Av) + (size_t)aphys[i] * lda + kc + q8;
                raf[i][0] = *(const float4*)Af;
                raf[i][1] = *(const float4*)(Af + 4);
            }
            rbf[i][0] = *(const float4*)(bp[i] + kc);
            rbf[i][1] = *(const float4*)(bp[i] + kc + 4);
        }
    };

    auto sts_chunk = [&](int s) {
        char* sa = sm + s * STAGE_BYTES;
        char* sb = sa + MAT_BYTES;
        #pragma unroll
        for (int i = 0; i < 4; i++) {
            if (AH) {
                *(uint4*)(sa + stoff[i]) = rah[i];
            } else {
                *(uint4*)(sa + stoff[i]) = make_uint4(
                    pack2(raf[i][0].x, raf[i][0].y), pack2(raf[i][0].z, raf[i][0].w),
                    pack2(raf[i][1].x, raf[i][1].y), pack2(raf[i][1].z, raf[i][1].w));
            }
            *(uint4*)(sb + stoff[i]) = make_uint4(
                pack2(rbf[i][0].x, rbf[i][0].y), pack2(rbf[i][0].z, rbf[i][0].w),
                pack2(rbf[i][1].x, rbf[i][1].y), pack2(rbf[i][1].z, rbf[i][1].w));
        }
    };

    // prolog: chunk0 -> stage0; chunk1 in regs
    load_chunk(0);
    sts_chunk(0);
    if (nch > 1) load_chunk(32);
    __syncthreads();

    for (int it = 0; it < nch; it++) {
        int s = it & 1;

        // stage s^1: store chunk it+1 (in regs), prefetch chunk it+2
        if (it + 1 < nch) {
            sts_chunk(s ^ 1);
            if (it + 2 < nch) load_chunk((it + 2) * 32);
        }

        // compute on stage s
        uint32_t sA = sbase + s * STAGE_BYTES;
        uint32_t sB = sA + MAT_BYTES;
        #pragma unroll
        for (int ks = 0; ks < 2; ks++) {
            unsigned af[4][4], bf[8][2];
            #pragma unroll
            for (int mt = 0; mt < 4; mt++)
                ldsm4(af[mt][0], af[mt][1], af[mt][2], af[mt][3],
                      sA + aoff[ks] + mt * 1024);
            #pragma unroll
            for (int np = 0; np < 4; np++) {
                unsigned t0, t1, t2, t3;
                ldsm4(t0, t1, t2, t3, sB + boff[ks] + np * 1024);
                bf[2 * np][0] = t0;     bf[2 * np][1] = t2;
                bf[2 * np + 1][0] = t1; bf[2 * np + 1][1] = t3;
            }
            #pragma unroll
            for (int mt = 0; mt < 4; mt++)
                #pragma unroll
                for (int nt = 0; nt < 8; nt++)
                    mma_f16(acc[mt][nt], af[mt], bf[nt], acc[mt][nt]);
        }
        __syncthreads();
    }

    // ---- epilogue ----
    #pragma unroll
    for (int mt = 0; mt < 4; mt++) {
        int row0 = m0 + mb + mt * 16 + grp;
        #pragma unroll
        for (int nt = 0; nt < 8; nt++) {
            int col = n0 + nb + nt * 8 + tig * 2;
            #pragma unroll
            for (int h = 0; h < 2; h++) {
                int row = row0 + h * 8;
                if (row >= M) continue;
                float v0 = acc[mt][nt][2 * h], v1 = acc[mt][nt][2 * h + 1];
                if (OH) {
                    __half2* p = (__half2*)(((__half*)Cv) + (size_t)(rowbase + row) * ldc + col);
                    if (FUSE) {
                        float2 u = __half22float2(*p);
                        v0 = (v0 / (1.f + __expf(-v0))) * u.x;
                        v1 = (v1 / (1.f + __expf(-v1))) * u.y;
                    }
                    *p = __floats2half2_rn(v0, v1);
                } else {
                    float* p = ((float*)Cv) + (size_t)(rowbase + row) * ldc + col;
                    p[0] = v0; p[1] = v1;
                }
            }
        }
    }
}

// out[t][d] += sum_k w(t,k) * eo[pos(t,k)][d]
__global__ void combine_kernel(float* __restrict__ out) {
    int t = blockIdx.y;
    int d = blockIdx.x * blockDim.x + threadIdx.x;
    float s = out[(size_t)t * ND + d];
    #pragma unroll
    for (int k = 0; k < TOPK; k++) {
        int p = g_a2p[t * TOPK + k];
        if (p >= 0) s += g_tw[t * TOPK + k] * g_eo[(size_t)p * ND + d];
    }
    out[(size_t)t * ND + d] = s;
}

// ---------------- launch ----------------
extern "C" void kernel_launch(void* const* d_in, const int* in_sizes, int n_in,
                              void* d_out, int out_size)
{
    const float* x       = (const float*)d_in[0];
    const float* gate_w  = (const float*)d_in[1];
    const float* w_gate  = (const float*)d_in[2];
    const float* w_up    = (const float*)d_in[3];
    const float* w_down  = (const float*)d_in[4];
    const float* sh_gate = (const float*)d_in[5];
    const float* sh_up   = (const float*)d_in[6];
    const float* sh_down = (const float*)d_in[7];
    float* out = (float*)d_out;

    void *pu, *peo, *psu, *pstok, *poff, *pcnt;
    cudaGetSymbolAddress(&pu,   g_u);
    cudaGetSymbolAddress(&peo,  g_eo);
    cudaGetSymbolAddress(&psu,  g_su);
    cudaGetSymbolAddress(&pstok, g_stok);
    cudaGetSymbolAddress(&poff, g_offsets);
    cudaGetSymbolAddress(&pcnt, g_counts);
    __half* ubuf = (__half*)pu;  float* eo = (float*)peo;  __half* su = (__half*)psu;
    int* stok = (int*)pstok;     int* offs = (int*)poff;   int* cnts = (int*)pcnt;

    // 1) router + dispatch
    zero_kernel<<<1, 64>>>();
    router_kernel<<<NTOK, 256>>>(x, gate_w);
    prefix_kernel<<<1, 1>>>();
    scatter_kernel<<<(NA + 255) / 256, 256>>>();

    // 2) routed experts: up -> ubuf(fp16); gate fused silu*u -> ubuf; down -> eo(fp32)
    {
        dim3 grid(NF / 128, CAP / 128, NE);
        gemm16<0,1,0><<<grid, 128>>>(x, ND, w_up,   ubuf, NF, 0, NF, ND, stok, offs, cnts);
        gemm16<0,1,1><<<grid, 128>>>(x, ND, w_gate, ubuf, NF, 0, NF, ND, stok, offs, cnts);
    }
    {
        dim3 grid(ND / 128, CAP / 128, NE);
        gemm16<1,0,0><<<grid, 128>>>(ubuf, NF, w_down, eo, ND, 0, ND, NF, nullptr, offs, cnts);
    }

    // 3) shared expert: up -> su(fp16); gate fused -> su; down -> out(fp32)
    {
        dim3 grid(NFS / 128, NTOK / 128, 1);
        gemm16<0,1,0><<<grid, 128>>>(x, ND, sh_up,   su, NFS, NTOK, NFS, ND, nullptr, nullptr, nullptr);
        gemm16<0,1,1><<<grid, 128>>>(x, ND, sh_gate, su, NFS, NTOK, NFS, ND, nullptr, nullptr, nullptr);
    }
    {
        dim3 grid(ND / 128, NTOK / 128, 1);
        gemm16<1,0,0><<<grid, 128>>>(su, NFS, sh_down, out, ND, NTOK, ND, NFS, nullptr, nullptr, nullptr);
    }

    // 4) combine routed outputs into d_out
    {
        dim3 grid(ND / 256, NTOK);
        combine_kernel<<<grid, 256>>>(out);
    }
}